// round 6
// baseline (speedup 1.0000x reference)
#include <cuda_runtime.h>
#include <math.h>

// Petrosian fractal features, 5 scales, T=4096, 57 windows/row.
// 2 rows per CTA (256 threads). Pure-register data path: each thread owns 16
// contiguous elements of each row (8x LDG.128 front-issued for MLP). Halo via
// shfl_down + 64B smem at warp boundaries. 128-elem segment sums via
// __reduce_add_sync; warp0/warp1 scan the 32 segment sums for row A/B in
// registers and produce all 57 outputs via shfl gathers (no 3rd barrier).
//   zc(window [128a,128b)) = S[b] - S[a] - s[128b-2] - s[128b-1]

#define T_LEN   4096
#define THREADS 256
#define PT      16
#define NSEG    32
#define N_WIN   57
#define ROWS    2

__global__ __launch_bounds__(THREADS)
void petrosian_kernel(const float* __restrict__ x, float* __restrict__ out) {
    __shared__ float halo[ROWS][8][2];
    __shared__ int   segsum[ROWS][NSEG];
    __shared__ int   bcorr[ROWS][NSEG + 1];

    const int row0 = blockIdx.x * ROWS;
    const int tid  = threadIdx.x;
    const int lane = tid & 31, wid = tid >> 5;
    const int base = tid * PT;
    const float4* a4 = (const float4*)(x + (size_t)row0 * T_LEN + base);
    const float4* b4 = (const float4*)((const float*)a4 + T_LEN);

    // ---- 8 front-issued LDG.128 (2 rows x 16 elements) ----
    float vA[PT], vB[PT];
    #pragma unroll
    for (int i = 0; i < 4; i++) {
        float4 t = a4[i];
        vA[4*i+0] = t.x; vA[4*i+1] = t.y; vA[4*i+2] = t.z; vA[4*i+3] = t.w;
    }
    #pragma unroll
    for (int i = 0; i < 4; i++) {
        float4 t = b4[i];
        vB[4*i+0] = t.x; vB[4*i+1] = t.y; vB[4*i+2] = t.z; vB[4*i+3] = t.w;
    }

    // halo candidates from next lane (lane 31 fixed up after the barrier)
    float hA0 = __shfl_down_sync(0xffffffffu, vA[0], 1);
    float hA1 = __shfl_down_sync(0xffffffffu, vA[1], 1);
    float hB0 = __shfl_down_sync(0xffffffffu, vB[0], 1);
    float hB1 = __shfl_down_sync(0xffffffffu, vB[1], 1);
    if (lane == 0) {
        halo[0][wid][0] = vA[0]; halo[0][wid][1] = vA[1];
        halo[1][wid][0] = vB[0]; halo[1][wid][1] = vB[1];
    }

    // ---- bulk indicators i = 0..13 for both rows ----
    int cntA = 0, cntB = 0;
    float dpA = vA[1] - vA[0];
    float dpB = vB[1] - vB[0];
    #pragma unroll
    for (int i = 0; i < PT - 2; i++) {
        float dnA = vA[i+2] - vA[i+1];
        float dnB = vB[i+2] - vB[i+1];
        cntA += (dpA * dnA < 0.0f) ? 1 : 0;
        cntB += (dpB * dnB < 0.0f) ? 1 : 0;
        dpA = dnA; dpB = dnB;
    }

    __syncthreads();   // halo[] visible

    if (lane == 31) {
        int nw = wid + 1;
        if (nw < 8) {
            hA0 = halo[0][nw][0]; hA1 = halo[0][nw][1];
            hB0 = halo[1][nw][0]; hB1 = halo[1][nw][1];
        } else {
            hA0 = hA1 = hB0 = hB1 = 0.0f;   // forced invalid below
        }
    }

    // ---- last two indicators (j = base+14, base+15) ----
    const int valid = (tid != THREADS - 1);
    float dA14 = hA0 - vA[15], dA15 = hA1 - hA0;
    float dB14 = hB0 - vB[15], dB15 = hB1 - hB0;
    int sA14 = (dpA  * dA14 < 0.0f) && valid;
    int sA15 = (dA14 * dA15 < 0.0f) && valid;
    int sB14 = (dpB  * dB14 < 0.0f) && valid;
    int sB15 = (dB14 * dB15 < 0.0f) && valid;
    cntA += sA14 + sA15;
    cntB += sB14 + sB15;

    // ---- 8-lane segment sums (segment = 8 threads = 128 elems) ----
    unsigned gmask = 0xFFu << (lane & 24);
    int ssA = __reduce_add_sync(gmask, cntA);
    int ssB = __reduce_add_sync(gmask, cntB);
    if ((tid & 7) == 7) {
        int seg = tid >> 3;
        segsum[0][seg] = ssA;  bcorr[0][seg + 1] = sA14 + sA15;
        segsum[1][seg] = ssB;  bcorr[1][seg + 1] = sB14 + sB15;
    }
    __syncthreads();

    // ---- warp r (r<2): scan row r's 32 segment sums in regs, emit outputs ----
    if (wid < ROWS) {
        const int r = wid;
        int sc = segsum[r][lane];              // lane l -> segsum[l]
        #pragma unroll
        for (int off = 1; off < 32; off <<= 1) {
            int n = __shfl_up_sync(0xffffffffu, sc, off);
            if (lane >= off) sc += n;          // sc = S[lane+1]
        }

        const size_t obase = (size_t)(row0 + r) * N_WIN;
        #pragma unroll
        for (int half = 0; half < 2; half++) {
            int k = lane + half * 32;
            int kk = (k < N_WIN) ? k : 0;
            int w, a; float L;
            if      (kk < 1)  { w = 4096; a = 0;              L = 3.612359948f; }
            else if (kk < 4)  { w = 2048; a = (kk - 1)  * 8;  L = 3.311329954f; }
            else if (kk < 11) { w = 1024; a = (kk - 4)  * 4;  L = 3.010299957f; }
            else if (kk < 26) { w = 512;  a = (kk - 11) * 2;  L = 2.709269961f; }
            else              { w = 256;  a = kk - 26;        L = 2.408239965f; }
            int b = a + (w >> 7);

            int Sb = __shfl_sync(0xffffffffu, sc, b - 1);
            int Sa = __shfl_sync(0xffffffffu, sc, (a > 0) ? (a - 1) : 0);
            if (a == 0) Sa = 0;

            if (k < N_WIN) {
                float zc = (float)(Sb - Sa - bcorr[r][b]);
                float wf = (float)w;
                float denom = L + log10f(wf / (wf + 0.4f * zc));
                out[obase + k] = L / denom;
            }
        }
    }
}

extern "C" void kernel_launch(void* const* d_in, const int* in_sizes, int n_in,
                              void* d_out, int out_size) {
    const float* x = (const float*)d_in[0];
    float* out = (float*)d_out;
    int n_blocks = in_sizes[0] / (T_LEN * ROWS);   // (B*C)/2 = 2048
    petrosian_kernel<<<n_blocks, THREADS>>>(x, out);
}